// round 6
// baseline (speedup 1.0000x reference)
#include <cuda_runtime.h>

#define NPIX 2304
#define Bn 4
#define Cn 256
#define HIDn 128
#define LOG2E 1.4426950408889634f

typedef unsigned long long ull;

__device__ __forceinline__ ull pack1(float a){ ull r; asm("mov.b64 %0, {%1,%1};" : "=l"(r) : "f"(a)); return r; }
__device__ __forceinline__ ull pack2(float a, float b){ ull r; asm("mov.b64 %0, {%1,%2};" : "=l"(r) : "f"(a), "f"(b)); return r; }
__device__ __forceinline__ float2 unpk(ull a){ float2 f; asm("mov.b64 {%0,%1}, %2;" : "=f"(f.x), "=f"(f.y) : "l"(a)); return f; }
__device__ __forceinline__ ull fma2(ull a, ull b, ull c){ ull d; asm("fma.rn.f32x2 %0, %1, %2, %3;" : "=l"(d) : "l"(a), "l"(b), "l"(c)); return d; }
__device__ __forceinline__ ull mul2p(ull a, ull b){ ull d; asm("mul.rn.f32x2 %0, %1, %2;" : "=l"(d) : "l"(a), "l"(b)); return d; }

// ---- scratch (device globals; no allocation allowed) ----
__device__ float d_lumaN[Bn*NPIX];
__device__ float d_bias2[Bn*NPIX];          // alpha*(pooled invL - mean)*log2(e)
__device__ float d_h1[Bn*HIDn*NPIX];        // relu(conv1)
__device__ float d_hm[Bn*HIDn];
__device__ float d_w2t[HIDn*9*HIDn];        // conv2 weights transposed [ic][k][oc]
__device__ float d_film[6*Bn*Cn];           // order: gq,bqf,gk,bkf,gv,bvf
__device__ float d_Q[Bn*8*NPIX*32];         // [bh][n][d], SCALE*log2e folded in
__device__ float d_Kt[Bn*8*32*NPIX];        // [bh][d][n]
__device__ float d_V[Bn*8*NPIX*32];         // [bh][n][d]
__device__ float d_O[Bn*Cn*NPIX];           // attention output [b][c][n]

// ============================================================
// Kernel 1: weight transpose for conv2 (coalesced oc-major)
// ============================================================
__global__ void transpose_w2_kernel(const float* __restrict__ w2){
    int idx = blockIdx.x*256 + threadIdx.x;
    if (idx < HIDn*HIDn*9){
        int oc = idx / (HIDn*9);
        int rem = idx - oc*(HIDn*9);
        int ic = rem / 9;
        int k  = rem - ic*9;
        d_w2t[(ic*9 + k)*HIDn + oc] = w2[idx];
    }
}

// ============================================================
// Kernel 2: luma + min/max normalize + pooled invL bias (+zero hm)
// grid = B, block = 256
// ============================================================
__global__ void luma_kernel(const float* __restrict__ rgb, const float* __restrict__ alphap){
    int b = blockIdx.x, tid = threadIdx.x;
    __shared__ float ys[NPIX];
    __shared__ float r0[8], r1[8], sc[2];

    if (tid < HIDn) d_hm[b*HIDn + tid] = 0.f;

    const float* R = rgb + b*3*NPIX;
    const float* G = R + NPIX;
    const float* Bl = G + NPIX;
    float mn = 1e30f, mx = -1e30f;
    #pragma unroll
    for (int i=0;i<9;i++){
        int n = i*256 + tid;
        float y = 0.299f*R[n] + 0.587f*G[n] + 0.114f*Bl[n];
        ys[n] = y; mn = fminf(mn, y); mx = fmaxf(mx, y);
    }
    #pragma unroll
    for (int off=16; off; off>>=1){
        mn = fminf(mn, __shfl_xor_sync(0xffffffffu, mn, off));
        mx = fmaxf(mx, __shfl_xor_sync(0xffffffffu, mx, off));
    }
    if ((tid & 31)==0){ r0[tid>>5]=mn; r1[tid>>5]=mx; }
    __syncthreads();
    if (tid==0){
        float a=r0[0], c=r1[0];
        for (int i=1;i<8;i++){ a=fminf(a,r0[i]); c=fmaxf(c,r1[i]); }
        sc[0]=a; sc[1]=c;
    }
    __syncthreads();
    float minv = sc[0];
    float invR = 1.f/(sc[1]-minv+1e-6f);

    float p9[9]; float tot = 0.f;
    #pragma unroll
    for (int i=0;i<9;i++){
        int n = i*256 + tid; int y = n/48, x = n - y*48;
        d_lumaN[b*NPIX + n] = (ys[n]-minv)*invR;
        float s = 0.f;
        for (int dy=-1; dy<=1; dy++){
            int yy=y+dy; if ((unsigned)yy<48u){
                for (int dx=-1; dx<=1; dx++){
                    int xx=x+dx; if ((unsigned)xx<48u) s += 1.f - (ys[yy*48+xx]-minv)*invR;
                }
            }
        }
        p9[i] = s * (1.f/9.f);
        tot += p9[i];
    }
    #pragma unroll
    for (int off=16; off; off>>=1) tot += __shfl_xor_sync(0xffffffffu, tot, off);
    __syncthreads();
    if ((tid & 31)==0) r0[tid>>5] = tot;
    __syncthreads();
    if (tid==0){ float a=0.f; for(int i=0;i<8;i++) a+=r0[i]; sc[0] = a * (1.f/NPIX); }
    __syncthreads();
    float mean = sc[0];
    float alpha = *alphap;
    #pragma unroll
    for (int i=0;i<9;i++){
        int n = i*256 + tid;
        d_bias2[b*NPIX + n] = alpha * (p9[i] - mean) * LOG2E;
    }
}

// ============================================================
// Kernel 3: conv1 (1->128 ch, 3x3, relu). grid (128, B), block 256
// ============================================================
__global__ void conv1_kernel(const float* __restrict__ w1, const float* __restrict__ b1){
    int oc = blockIdx.x, b = blockIdx.y, tid = threadIdx.x;
    __shared__ float ls[NPIX];
    #pragma unroll
    for (int i=0;i<9;i++) ls[i*256+tid] = d_lumaN[b*NPIX + i*256 + tid];
    __syncthreads();
    float w[9];
    #pragma unroll
    for (int t=0;t<9;t++) w[t] = w1[oc*9+t];
    float bias = b1[oc];
    #pragma unroll
    for (int i=0;i<9;i++){
        int n = i*256+tid; int y = n/48, x = n-y*48;
        float acc = bias;
        #pragma unroll
        for (int dy=-1;dy<=1;dy++){
            int yy=y+dy; if((unsigned)yy<48u){
                #pragma unroll
                for (int dx=-1;dx<=1;dx++){
                    int xx=x+dx; if((unsigned)xx<48u) acc += w[(dy+1)*3+dx+1]*ls[yy*48+xx];
                }
            }
        }
        d_h1[(b*HIDn+oc)*NPIX + n] = fmaxf(acc, 0.f);
    }
}

// ============================================================
// Kernel 4: conv2 (128->128 3x3) + relu + spatial mean.
// grid (48 rows, B), block 256: thread = (oc, half-row of 24 px)
// ============================================================
__global__ __launch_bounds__(256) void conv2_kernel(const float* __restrict__ b2){
    int y = blockIdx.x, b = blockIdx.y, tid = threadIdx.x;
    __shared__ float in_s[64][3][50];   // 64-ic chunk, rows y-1..y+1, cols padded
    __shared__ float red[256];
    int oc = tid & 127;
    int xb = (tid>>7)*24;
    float acc[24];
    #pragma unroll
    for (int p=0;p<24;p++) acc[p]=0.f;

    for (int chunk=0; chunk<2; chunk++){
        int ic0 = chunk*64;
        __syncthreads();
        for (int j = tid; j < 64*3; j += 256){ in_s[j/3][j%3][0]=0.f; in_s[j/3][j%3][49]=0.f; }
        for (int idx = tid; idx < 64*3*48; idx += 256){
            int ic = idx/144; int rem = idx - ic*144; int r = rem/48; int x = rem - r*48;
            int yy = y + r - 1;
            float v = 0.f;
            if ((unsigned)yy < 48u) v = d_h1[(b*HIDn + ic0 + ic)*NPIX + yy*48 + x];
            in_s[ic][r][x+1] = v;
        }
        __syncthreads();
        #pragma unroll 1
        for (int ic=0; ic<64; ic++){
            const float* wrow = d_w2t + (ic0+ic)*9*HIDn + oc;
            #pragma unroll
            for (int r=0;r<3;r++){
                float w0 = wrow[r*384], w1 = wrow[r*384+128], w2v = wrow[r*384+256];
                const float* row = &in_s[ic][r][xb];
                float v[26];
                #pragma unroll
                for (int p=0;p<26;p++) v[p]=row[p];
                #pragma unroll
                for (int p=0;p<24;p++) acc[p] += w0*v[p] + w1*v[p+1] + w2v*v[p+2];
            }
        }
    }
    float bias = b2[oc];
    float s = 0.f;
    #pragma unroll
    for (int p=0;p<24;p++) s += fmaxf(acc[p]+bias, 0.f);
    red[tid] = s;
    __syncthreads();
    if (tid < 128){
        float t = red[tid] + red[tid+128];
        atomicAdd(&d_hm[b*HIDn + tid], t*(1.f/NPIX));
    }
}

// ============================================================
// Kernel 5: FiLM params. grid (6, B), block 256 (thread = out channel)
// ============================================================
__global__ void film_kernel(const float* gq_w,const float* gq_b,const float* bqf_w,const float* bqf_b,
                            const float* gk_w,const float* gk_b,const float* bkf_w,const float* bkf_b,
                            const float* gv_w,const float* gv_b,const float* bvf_w,const float* bvf_b){
    int p = blockIdx.x, b = blockIdx.y, o = threadIdx.x;
    __shared__ float hs[HIDn];
    if (o < HIDn) hs[o] = d_hm[b*HIDn + o];
    __syncthreads();
    const float* W; const float* Bp;
    switch(p){
        case 0: W=gq_w;  Bp=gq_b;  break;
        case 1: W=bqf_w; Bp=bqf_b; break;
        case 2: W=gk_w;  Bp=gk_b;  break;
        case 3: W=bkf_w; Bp=bkf_b; break;
        case 4: W=gv_w;  Bp=gv_b;  break;
        default: W=bvf_w; Bp=bvf_b; break;
    }
    float acc = Bp[o];
    #pragma unroll 4
    for (int k=0;k<HIDn;k++) acc += hs[k]*W[o*HIDn+k];
    d_film[(p*Bn + b)*Cn + o] = acc;
}

// ============================================================
// Kernel 6: QKV projection + FiLM. Tiled GEMM 64x64x16, f32x2 microkernel.
// grid (36 ntiles, 4 otiles, B*3), block 256
// ============================================================
__global__ __launch_bounds__(256) void qkv_kernel(const float* __restrict__ x,
        const float* __restrict__ wq, const float* __restrict__ bq,
        const float* __restrict__ wk, const float* __restrict__ bk,
        const float* __restrict__ wv, const float* __restrict__ bv){
    int z = blockIdx.z; int b = z/3, w = z - b*3;
    const float* W; const float* Bi;
    if (w==0){W=wq;Bi=bq;} else if (w==1){W=wk;Bi=bk;} else {W=wv;Bi=bv;}
    const float* X = x + b*Cn*NPIX;
    __shared__ __align__(16) float As[16][68];
    __shared__ __align__(16) float Bs[16][64];
    int tid = threadIdx.x;
    int tx = tid & 15, ty = tid >> 4;
    int o0 = blockIdx.y*64, n0 = blockIdx.x*64;
    ull acc2[4][2];
    #pragma unroll
    for (int i=0;i<4;i++){ acc2[i][0]=0ull; acc2[i][1]=0ull; }
    int ra = tid >> 2, ca = tid & 3;
    int rb = tid >> 4, cb = tid & 15;
    for (int k0=0;k0<Cn;k0+=16){
        float4 a4 = *(const float4*)&W[(o0+ra)*Cn + k0 + ca*4];
        float4 b4 = *(const float4*)&X[(k0+rb)*NPIX + n0 + cb*4];
        As[ca*4+0][ra]=a4.x; As[ca*4+1][ra]=a4.y; As[ca*4+2][ra]=a4.z; As[ca*4+3][ra]=a4.w;
        *(float4*)&Bs[rb][cb*4] = b4;
        __syncthreads();
        #pragma unroll
        for (int k=0;k<16;k++){
            float4 bb4 = *(const float4*)&Bs[k][tx*4];
            ull bb0 = pack2(bb4.x, bb4.y), bb1 = pack2(bb4.z, bb4.w);
            float4 aa4 = *(const float4*)&As[k][ty*4];
            ull a0=pack1(aa4.x),a1=pack1(aa4.y),a2=pack1(aa4.z),a3=pack1(aa4.w);
            acc2[0][0]=fma2(a0,bb0,acc2[0][0]); acc2[0][1]=fma2(a0,bb1,acc2[0][1]);
            acc2[1][0]=fma2(a1,bb0,acc2[1][0]); acc2[1][1]=fma2(a1,bb1,acc2[1][1]);
            acc2[2][0]=fma2(a2,bb0,acc2[2][0]); acc2[2][1]=fma2(a2,bb1,acc2[2][1]);
            acc2[3][0]=fma2(a3,bb0,acc2[3][0]); acc2[3][1]=fma2(a3,bb1,acc2[3][1]);
        }
        __syncthreads();
    }
    const float* gvec = d_film + ((2*w)*Bn + b)*Cn;
    const float* tvec = d_film + ((2*w+1)*Bn + b)*Cn;
    float vals[4][4];
    #pragma unroll
    for (int i=0;i<4;i++){
        int o = o0 + ty*4 + i;
        float g = gvec[o], bt = tvec[o], bo = Bi[o];
        float2 u0 = unpk(acc2[i][0]), u1 = unpk(acc2[i][1]);
        float tmp[4] = {u0.x,u0.y,u1.x,u1.y};
        #pragma unroll
        for (int j=0;j<4;j++){
            float vv = g*(tmp[j]+bo) + bt;
            if (w==0) vv *= (1.4426950408889634f*0.17677669529663687f); // log2e/sqrt(32) folded into Q
            vals[i][j]=vv;
        }
    }
    int obase = o0 + ty*4;
    int h = obase >> 5, d0 = obase & 31;
    int bh = b*8 + h;
    if (w==1){
        #pragma unroll
        for (int i=0;i<4;i++)
            *(float4*)&d_Kt[(bh*32 + d0 + i)*NPIX + n0 + tx*4] =
                make_float4(vals[i][0],vals[i][1],vals[i][2],vals[i][3]);
    } else {
        float* Dst = (w==0) ? d_Q : d_V;
        #pragma unroll
        for (int j=0;j<4;j++){
            int n = n0 + tx*4 + j;
            *(float4*)&Dst[(bh*NPIX + n)*32 + d0] =
                make_float4(vals[0][j],vals[1][j],vals[2][j],vals[3][j]);
        }
    }
}

// ============================================================
// Kernel 7: flash attention, fp32, f32x2 inner loops.
// grid (18, B*HEADS), block 128: thread = one query row
// ============================================================
__global__ __launch_bounds__(128) void attn_kernel(){
    int bh = blockIdx.y; int b = bh >> 3; int h = bh & 7;
    int tid = threadIdx.x;
    int n = blockIdx.x*128 + tid;
    __shared__ __align__(16) float Ks[32][36];
    __shared__ __align__(16) float Vs[32][36];
    __shared__ float bS[32];

    const float* Qr = d_Q + (bh*NPIX + n)*32;
    float q[32];
    #pragma unroll
    for (int i=0;i<8;i++){
        float4 t = *(const float4*)&Qr[i*4];
        q[i*4]=t.x; q[i*4+1]=t.y; q[i*4+2]=t.z; q[i*4+3]=t.w;
    }
    float m = -1e30f, l = 0.f;
    ull o2[16];
    #pragma unroll
    for (int i=0;i<16;i++) o2[i]=0ull;
    const float* KtB = d_Kt + bh*32*NPIX;
    const float* VB  = d_V  + bh*NPIX*32;
    const float* bb  = d_bias2 + b*NPIX;
    int rl = tid >> 2, cl = tid & 3;

    for (int t0=0; t0<NPIX; t0+=32){
        // Ks[d][j] = K^T[d][t0+j]  (column index j = token within tile)
        *(float4*)&Ks[rl][cl*4]      = *(const float4*)&KtB[rl*NPIX + t0 + cl*4];
        *(float4*)&Ks[rl][cl*4 + 16] = *(const float4*)&KtB[rl*NPIX + t0 + cl*4 + 16];
        // Vs[j][d] = V[t0+j][d]    (column index = dim; +16 applies to the DIM)
        *(float4*)&Vs[rl][cl*4]      = *(const float4*)&VB[(t0+rl)*32 + cl*4];
        *(float4*)&Vs[rl][cl*4 + 16] = *(const float4*)&VB[(t0+rl)*32 + cl*4 + 16];
        if (tid < 32) bS[tid] = bb[t0+tid];
        __syncthreads();

        // --- QK^T: s[j] for 32 keys, pairs via f32x2 ---
        ull s2[16];
        #pragma unroll
        for (int i=0;i<16;i++) s2[i]=0ull;
        #pragma unroll
        for (int d=0; d<32; d++){
            ull aa = pack1(q[d]);
            const ulonglong2* kr = (const ulonglong2*)&Ks[d][0];
            #pragma unroll
            for (int c=0;c<8;c++){
                ulonglong2 kk = kr[c];
                s2[2*c]   = fma2(aa, kk.x, s2[2*c]);
                s2[2*c+1] = fma2(aa, kk.y, s2[2*c+1]);
            }
        }
        // --- online softmax (base-2; scale folded into Q, bias includes log2e) ---
        float p[32];
        #pragma unroll
        for (int i=0;i<16;i++){
            float2 u = unpk(s2[i]);
            p[2*i]   = u.x + bS[2*i];
            p[2*i+1] = u.y + bS[2*i+1];
        }
        float mx = m;
        #pragma unroll
        for (int j=0;j<32;j++) mx = fmaxf(mx, p[j]);
        float corr = exp2f(m - mx); m = mx;
        float sum = 0.f;
        #pragma unroll
        for (int j=0;j<32;j++){ p[j] = exp2f(p[j]-m); sum += p[j]; }
        l = l*corr + sum;
        ull cc = pack1(corr);
        #pragma unroll
        for (int i=0;i<16;i++) o2[i]=mul2p(o2[i],cc);
        // --- PV ---
        #pragma unroll
        for (int j=0;j<32;j++){
            ull pp = pack1(p[j]);
            const ulonglong2* vr = (const ulonglong2*)&Vs[j][0];
            #pragma unroll
            for (int c=0;c<8;c++){
                ulonglong2 vv = vr[c];
                o2[2*c]   = fma2(pp, vv.x, o2[2*c]);
                o2[2*c+1] = fma2(pp, vv.y, o2[2*c+1]);
            }
        }
        __syncthreads();
    }
    float inv = 1.f/l;
    float* Orow = d_O + (b*Cn + h*32)*NPIX + n;
    #pragma unroll
    for (int i=0;i<16;i++){
        float2 u = unpk(o2[i]);
        Orow[(2*i)*NPIX]   = u.x*inv;
        Orow[(2*i+1)*NPIX] = u.y*inv;
    }
}

// ============================================================
// Kernel 8: output projection. Same GEMM scheme. grid (36,4,B)
// ============================================================
__global__ __launch_bounds__(256) void proj_kernel(const float* __restrict__ wproj,
        const float* __restrict__ bproj, float* __restrict__ out){
    int b = blockIdx.z;
    const float* X = d_O + b*Cn*NPIX;
    const float* W = wproj;
    __shared__ __align__(16) float As[16][68];
    __shared__ __align__(16) float Bs[16][64];
    int tid = threadIdx.x;
    int tx = tid & 15, ty = tid >> 4;
    int o0 = blockIdx.y*64, n0 = blockIdx.x*64;
    ull acc2[4][2];
    #pragma unroll
    for (int i=0;i<4;i++){ acc2[i][0]=0ull; acc2[i][1]=0ull; }
    int ra = tid >> 2, ca = tid & 3;
    int rb = tid >> 4, cb = tid & 15;
    for (int k0=0;k0<Cn;k0+=16){
        float4 a4 = *(const float4*)&W[(o0+ra)*Cn + k0 + ca*4];
        float4 b4 = *(const float4*)&X[(k0+rb)*NPIX + n0 + cb*4];
        As[ca*4+0][ra]=a4.x; As[ca*4+1][ra]=a4.y; As[ca*4+2][ra]=a4.z; As[ca*4+3][ra]=a4.w;
        *(float4*)&Bs[rb][cb*4] = b4;
        __syncthreads();
        #pragma unroll
        for (int k=0;k<16;k++){
            float4 bb4 = *(const float4*)&Bs[k][tx*4];
            ull bb0 = pack2(bb4.x, bb4.y), bb1 = pack2(bb4.z, bb4.w);
            float4 aa4 = *(const float4*)&As[k][ty*4];
            ull a0=pack1(aa4.x),a1=pack1(aa4.y),a2=pack1(aa4.z),a3=pack1(aa4.w);
            acc2[0][0]=fma2(a0,bb0,acc2[0][0]); acc2[0][1]=fma2(a0,bb1,acc2[0][1]);
            acc2[1][0]=fma2(a1,bb0,acc2[1][0]); acc2[1][1]=fma2(a1,bb1,acc2[1][1]);
            acc2[2][0]=fma2(a2,bb0,acc2[2][0]); acc2[2][1]=fma2(a2,bb1,acc2[2][1]);
            acc2[3][0]=fma2(a3,bb0,acc2[3][0]); acc2[3][1]=fma2(a3,bb1,acc2[3][1]);
        }
        __syncthreads();
    }
    #pragma unroll
    for (int i=0;i<4;i++){
        int o = o0 + ty*4 + i;
        float bo = bproj[o];
        float2 u0 = unpk(acc2[i][0]), u1 = unpk(acc2[i][1]);
        *(float4*)&out[(b*Cn+o)*NPIX + n0 + tx*4] =
            make_float4(u0.x+bo, u0.y+bo, u1.x+bo, u1.y+bo);
    }
}

// ============================================================
extern "C" void kernel_launch(void* const* d_in, const int* in_sizes, int n_in,
                              void* d_out, int out_size){
    const float* x      = (const float*)d_in[0];
    const float* rgb    = (const float*)d_in[1];
    const float* wq     = (const float*)d_in[2];
    const float* bq     = (const float*)d_in[3];
    const float* wk     = (const float*)d_in[4];
    const float* bk     = (const float*)d_in[5];
    const float* wv     = (const float*)d_in[6];
    const float* bv     = (const float*)d_in[7];
    const float* wproj  = (const float*)d_in[8];
    const float* bproj  = (const float*)d_in[9];
    const float* c1_w   = (const float*)d_in[10];
    const float* c1_b   = (const float*)d_in[11];
    const float* c2_w   = (const float*)d_in[12];
    const float* c2_b   = (const float*)d_in[13];
    const float* gq_w   = (const float*)d_in[14];
    const float* gq_b   = (const float*)d_in[15];
    const float* bqf_w  = (const float*)d_in[16];
    const float* bqf_b  = (const float*)d_in[17];
    const float* gk_w   = (const float*)d_in[18];
    const float* gk_b   = (const float*)d_in[19];
    const float* bkf_w  = (const float*)d_in[20];
    const float* bkf_b  = (const float*)d_in[21];
    const float* gv_w   = (const float*)d_in[22];
    const float* gv_b   = (const float*)d_in[23];
    const float* bvf_w  = (const float*)d_in[24];
    const float* bvf_b  = (const float*)d_in[25];
    const float* alpha  = (const float*)d_in[26];
    float* out = (float*)d_out;

    transpose_w2_kernel<<<(HIDn*HIDn*9 + 255)/256, 256>>>(c2_w);
    luma_kernel<<<Bn, 256>>>(rgb, alpha);
    conv1_kernel<<<dim3(HIDn, Bn), 256>>>(c1_w, c1_b);
    conv2_kernel<<<dim3(48, Bn), 256>>>(c2_b);
    film_kernel<<<dim3(6, Bn), 256>>>(gq_w, gq_b, bqf_w, bqf_b,
                                      gk_w, gk_b, bkf_w, bkf_b,
                                      gv_w, gv_b, bvf_w, bvf_b);
    qkv_kernel<<<dim3(NPIX/64, Cn/64, Bn*3), 256>>>(x, wq, bq, wk, bk, wv, bv);
    attn_kernel<<<dim3(NPIX/128, Bn*8), 128>>>();
    proj_kernel<<<dim3(NPIX/64, Cn/64, Bn), 256>>>(wproj, bproj, out);
}

// round 11
// speedup vs baseline: 1.0331x; 1.0331x over previous
#include <cuda_runtime.h>

#define NPIX 2304
#define Bn 4
#define Cn 256
#define HIDn 128
#define LOG2E 1.4426950408889634f

typedef unsigned long long ull;

__device__ __forceinline__ ull pack1(float a){ ull r; asm("mov.b64 %0, {%1,%1};" : "=l"(r) : "f"(a)); return r; }
__device__ __forceinline__ ull pack2(float a, float b){ ull r; asm("mov.b64 %0, {%1,%2};" : "=l"(r) : "f"(a), "f"(b)); return r; }
__device__ __forceinline__ float2 unpk(ull a){ float2 f; asm("mov.b64 {%0,%1}, %2;" : "=f"(f.x), "=f"(f.y) : "l"(a)); return f; }
__device__ __forceinline__ ull fma2(ull a, ull b, ull c){ ull d; asm("fma.rn.f32x2 %0, %1, %2, %3;" : "=l"(d) : "l"(a), "l"(b), "l"(c)); return d; }
__device__ __forceinline__ ull mul2p(ull a, ull b){ ull d; asm("mul.rn.f32x2 %0, %1, %2;" : "=l"(d) : "l"(a), "l"(b)); return d; }

// ---- scratch (device globals; no allocation allowed) ----
__device__ float d_lumaN[Bn*NPIX];
__device__ float d_bias2[Bn*NPIX];          // alpha*(pooled invL - mean)*log2(e)
__device__ float d_h1[Bn*HIDn*NPIX];        // relu(conv1)
__device__ float d_hm[Bn*HIDn];
__device__ float d_w2t[HIDn*9*HIDn];        // conv2 weights transposed [ic][k][oc]
__device__ float d_film[6*Bn*Cn];           // order: gq,bqf,gk,bkf,gv,bvf
__device__ float d_Q[Bn*8*NPIX*32];         // [bh][n][d], SCALE*log2e folded in
__device__ float d_Kt[Bn*8*32*NPIX];        // [bh][d][n]
__device__ float d_V[Bn*8*NPIX*32];         // [bh][n][d]
__device__ float d_O[Bn*Cn*NPIX];           // attention output [b][c][n]

// ============================================================
// Kernel 1: weight transpose for conv2 (coalesced oc-major)
// ============================================================
__global__ void transpose_w2_kernel(const float* __restrict__ w2){
    int idx = blockIdx.x*256 + threadIdx.x;
    if (idx < HIDn*HIDn*9){
        int oc = idx / (HIDn*9);
        int rem = idx - oc*(HIDn*9);
        int ic = rem / 9;
        int k  = rem - ic*9;
        d_w2t[(ic*9 + k)*HIDn + oc] = w2[idx];
    }
}

// ============================================================
// Kernel 2: luma + min/max normalize + pooled invL bias (+zero hm)
// grid = B, block = 256
// ============================================================
__global__ void luma_kernel(const float* __restrict__ rgb, const float* __restrict__ alphap){
    int b = blockIdx.x, tid = threadIdx.x;
    __shared__ float ys[NPIX];
    __shared__ float r0[8], r1[8], sc[2];

    if (tid < HIDn) d_hm[b*HIDn + tid] = 0.f;

    const float* R = rgb + b*3*NPIX;
    const float* G = R + NPIX;
    const float* Bl = G + NPIX;
    float mn = 1e30f, mx = -1e30f;
    #pragma unroll
    for (int i=0;i<9;i++){
        int n = i*256 + tid;
        float y = 0.299f*R[n] + 0.587f*G[n] + 0.114f*Bl[n];
        ys[n] = y; mn = fminf(mn, y); mx = fmaxf(mx, y);
    }
    #pragma unroll
    for (int off=16; off; off>>=1){
        mn = fminf(mn, __shfl_xor_sync(0xffffffffu, mn, off));
        mx = fmaxf(mx, __shfl_xor_sync(0xffffffffu, mx, off));
    }
    if ((tid & 31)==0){ r0[tid>>5]=mn; r1[tid>>5]=mx; }
    __syncthreads();
    if (tid==0){
        float a=r0[0], c=r1[0];
        for (int i=1;i<8;i++){ a=fminf(a,r0[i]); c=fmaxf(c,r1[i]); }
        sc[0]=a; sc[1]=c;
    }
    __syncthreads();
    float minv = sc[0];
    float invR = 1.f/(sc[1]-minv+1e-6f);

    float p9[9]; float tot = 0.f;
    #pragma unroll
    for (int i=0;i<9;i++){
        int n = i*256 + tid; int y = n/48, x = n - y*48;
        d_lumaN[b*NPIX + n] = (ys[n]-minv)*invR;
        float s = 0.f;
        for (int dy=-1; dy<=1; dy++){
            int yy=y+dy; if ((unsigned)yy<48u){
                for (int dx=-1; dx<=1; dx++){
                    int xx=x+dx; if ((unsigned)xx<48u) s += 1.f - (ys[yy*48+xx]-minv)*invR;
                }
            }
        }
        p9[i] = s * (1.f/9.f);
        tot += p9[i];
    }
    #pragma unroll
    for (int off=16; off; off>>=1) tot += __shfl_xor_sync(0xffffffffu, tot, off);
    __syncthreads();
    if ((tid & 31)==0) r0[tid>>5] = tot;
    __syncthreads();
    if (tid==0){ float a=0.f; for(int i=0;i<8;i++) a+=r0[i]; sc[0] = a * (1.f/NPIX); }
    __syncthreads();
    float mean = sc[0];
    float alpha = *alphap;
    #pragma unroll
    for (int i=0;i<9;i++){
        int n = i*256 + tid;
        d_bias2[b*NPIX + n] = alpha * (p9[i] - mean) * LOG2E;
    }
}

// ============================================================
// Kernel 3: conv1 (1->128 ch, 3x3, relu). grid (128, B), block 256
// ============================================================
__global__ void conv1_kernel(const float* __restrict__ w1, const float* __restrict__ b1){
    int oc = blockIdx.x, b = blockIdx.y, tid = threadIdx.x;
    __shared__ float ls[NPIX];
    #pragma unroll
    for (int i=0;i<9;i++) ls[i*256+tid] = d_lumaN[b*NPIX + i*256 + tid];
    __syncthreads();
    float w[9];
    #pragma unroll
    for (int t=0;t<9;t++) w[t] = w1[oc*9+t];
    float bias = b1[oc];
    #pragma unroll
    for (int i=0;i<9;i++){
        int n = i*256+tid; int y = n/48, x = n-y*48;
        float acc = bias;
        #pragma unroll
        for (int dy=-1;dy<=1;dy++){
            int yy=y+dy; if((unsigned)yy<48u){
                #pragma unroll
                for (int dx=-1;dx<=1;dx++){
                    int xx=x+dx; if((unsigned)xx<48u) acc += w[(dy+1)*3+dx+1]*ls[yy*48+xx];
                }
            }
        }
        d_h1[(b*HIDn+oc)*NPIX + n] = fmaxf(acc, 0.f);
    }
}

// ============================================================
// Kernel 4: conv2 (128->128 3x3) + relu + spatial mean.
// RESTRUCTURED: grid (48 rows, 2 oc-halves, B) = 384 blocks.
// block 256 = 64 oc (tid&63) x 4 x-segments of 12 px (tid>>6).
// Weight prefetch: ic+1's 9 weights load during ic's 108 FMAs.
// ============================================================
__global__ __launch_bounds__(256) void conv2_kernel(const float* __restrict__ b2){
    int y = blockIdx.x, b = blockIdx.z, tid = threadIdx.x;
    int oc_base = blockIdx.y*64;
    __shared__ float in_s[64][3][50];   // 64-ic chunk, rows y-1..y+1, cols padded
    __shared__ float red[256];
    int oc = tid & 63;
    int xb = (tid>>6)*12;
    float acc[12];
    #pragma unroll
    for (int p=0;p<12;p++) acc[p]=0.f;

    for (int chunk=0; chunk<2; chunk++){
        int ic0 = chunk*64;
        __syncthreads();
        for (int j = tid; j < 64*3; j += 256){ in_s[j/3][j%3][0]=0.f; in_s[j/3][j%3][49]=0.f; }
        for (int idx = tid; idx < 64*3*48; idx += 256){
            int ic = idx/144; int rem = idx - ic*144; int r = rem/48; int x = rem - r*48;
            int yy = y + r - 1;
            float v = 0.f;
            if ((unsigned)yy < 48u) v = d_h1[(b*HIDn + ic0 + ic)*NPIX + yy*48 + x];
            in_s[ic][r][x+1] = v;
        }
        __syncthreads();
        const float* wbase = d_w2t + ic0*9*HIDn + oc_base + oc;
        float wn[9];
        #pragma unroll
        for (int k=0;k<9;k++) wn[k] = wbase[k*HIDn];
        #pragma unroll 1
        for (int ic=0; ic<64; ic++){
            float wc[9];
            #pragma unroll
            for (int k=0;k<9;k++) wc[k]=wn[k];
            if (ic < 63){
                const float* wp = wbase + (ic+1)*9*HIDn;
                #pragma unroll
                for (int k=0;k<9;k++) wn[k] = wp[k*HIDn];
            }
            #pragma unroll
            for (int r=0;r<3;r++){
                const float* row = &in_s[ic][r][xb];
                float v[14];
                #pragma unroll
                for (int p=0;p<14;p++) v[p]=row[p];
                #pragma unroll
                for (int p=0;p<12;p++)
                    acc[p] += wc[r*3]*v[p] + wc[r*3+1]*v[p+1] + wc[r*3+2]*v[p+2];
            }
        }
    }
    float bias = b2[oc_base + oc];
    float s = 0.f;
    #pragma unroll
    for (int p=0;p<12;p++) s += fmaxf(acc[p]+bias, 0.f);
    red[tid] = s;
    __syncthreads();
    if (tid < 64){
        float t = red[tid] + red[tid+64] + red[tid+128] + red[tid+192];
        atomicAdd(&d_hm[b*HIDn + oc_base + tid], t*(1.f/NPIX));
    }
}

// ============================================================
// Kernel 5: FiLM params. grid (6, B), block 256 (thread = out channel)
// ============================================================
__global__ void film_kernel(const float* gq_w,const float* gq_b,const float* bqf_w,const float* bqf_b,
                            const float* gk_w,const float* gk_b,const float* bkf_w,const float* bkf_b,
                            const float* gv_w,const float* gv_b,const float* bvf_w,const float* bvf_b){
    int p = blockIdx.x, b = blockIdx.y, o = threadIdx.x;
    __shared__ float hs[HIDn];
    if (o < HIDn) hs[o] = d_hm[b*HIDn + o];
    __syncthreads();
    const float* W; const float* Bp;
    switch(p){
        case 0: W=gq_w;  Bp=gq_b;  break;
        case 1: W=bqf_w; Bp=bqf_b; break;
        case 2: W=gk_w;  Bp=gk_b;  break;
        case 3: W=bkf_w; Bp=bkf_b; break;
        case 4: W=gv_w;  Bp=gv_b;  break;
        default: W=bvf_w; Bp=bvf_b; break;
    }
    float acc = Bp[o];
    #pragma unroll 4
    for (int k=0;k<HIDn;k++) acc += hs[k]*W[o*HIDn+k];
    d_film[(p*Bn + b)*Cn + o] = acc;
}

// ============================================================
// Kernel 6: QKV projection + FiLM. Tiled GEMM 64x64x16, f32x2 microkernel.
// grid (36 ntiles, 4 otiles, B*3), block 256
// ============================================================
__global__ __launch_bounds__(256) void qkv_kernel(const float* __restrict__ x,
        const float* __restrict__ wq, const float* __restrict__ bq,
        const float* __restrict__ wk, const float* __restrict__ bk,
        const float* __restrict__ wv, const float* __restrict__ bv){
    int z = blockIdx.z; int b = z/3, w = z - b*3;
    const float* W; const float* Bi;
    if (w==0){W=wq;Bi=bq;} else if (w==1){W=wk;Bi=bk;} else {W=wv;Bi=bv;}
    const float* X = x + b*Cn*NPIX;
    __shared__ __align__(16) float As[16][68];
    __shared__ __align__(16) float Bs[16][64];
    int tid = threadIdx.x;
    int tx = tid & 15, ty = tid >> 4;
    int o0 = blockIdx.y*64, n0 = blockIdx.x*64;
    ull acc2[4][2];
    #pragma unroll
    for (int i=0;i<4;i++){ acc2[i][0]=0ull; acc2[i][1]=0ull; }
    int ra = tid >> 2, ca = tid & 3;
    int rb = tid >> 4, cb = tid & 15;
    for (int k0=0;k0<Cn;k0+=16){
        float4 a4 = *(const float4*)&W[(o0+ra)*Cn + k0 + ca*4];
        float4 b4 = *(const float4*)&X[(k0+rb)*NPIX + n0 + cb*4];
        As[ca*4+0][ra]=a4.x; As[ca*4+1][ra]=a4.y; As[ca*4+2][ra]=a4.z; As[ca*4+3][ra]=a4.w;
        *(float4*)&Bs[rb][cb*4] = b4;
        __syncthreads();
        #pragma unroll
        for (int k=0;k<16;k++){
            float4 bb4 = *(const float4*)&Bs[k][tx*4];
            ull bb0 = pack2(bb4.x, bb4.y), bb1 = pack2(bb4.z, bb4.w);
            float4 aa4 = *(const float4*)&As[k][ty*4];
            ull a0=pack1(aa4.x),a1=pack1(aa4.y),a2=pack1(aa4.z),a3=pack1(aa4.w);
            acc2[0][0]=fma2(a0,bb0,acc2[0][0]); acc2[0][1]=fma2(a0,bb1,acc2[0][1]);
            acc2[1][0]=fma2(a1,bb0,acc2[1][0]); acc2[1][1]=fma2(a1,bb1,acc2[1][1]);
            acc2[2][0]=fma2(a2,bb0,acc2[2][0]); acc2[2][1]=fma2(a2,bb1,acc2[2][1]);
            acc2[3][0]=fma2(a3,bb0,acc2[3][0]); acc2[3][1]=fma2(a3,bb1,acc2[3][1]);
        }
        __syncthreads();
    }
    const float* gvec = d_film + ((2*w)*Bn + b)*Cn;
    const float* tvec = d_film + ((2*w+1)*Bn + b)*Cn;
    float vals[4][4];
    #pragma unroll
    for (int i=0;i<4;i++){
        int o = o0 + ty*4 + i;
        float g = gvec[o], bt = tvec[o], bo = Bi[o];
        float2 u0 = unpk(acc2[i][0]), u1 = unpk(acc2[i][1]);
        float tmp[4] = {u0.x,u0.y,u1.x,u1.y};
        #pragma unroll
        for (int j=0;j<4;j++){
            float vv = g*(tmp[j]+bo) + bt;
            if (w==0) vv *= (1.4426950408889634f*0.17677669529663687f); // log2e/sqrt(32) folded into Q
            vals[i][j]=vv;
        }
    }
    int obase = o0 + ty*4;
    int h = obase >> 5, d0 = obase & 31;
    int bh = b*8 + h;
    if (w==1){
        #pragma unroll
        for (int i=0;i<4;i++)
            *(float4*)&d_Kt[(bh*32 + d0 + i)*NPIX + n0 + tx*4] =
                make_float4(vals[i][0],vals[i][1],vals[i][2],vals[i][3]);
    } else {
        float* Dst = (w==0) ? d_Q : d_V;
        #pragma unroll
        for (int j=0;j<4;j++){
            int n = n0 + tx*4 + j;
            *(float4*)&Dst[(bh*NPIX + n)*32 + d0] =
                make_float4(vals[0][j],vals[1][j],vals[2][j],vals[3][j]);
        }
    }
}

// ============================================================
// Kernel 7: flash attention, fp32, f32x2 inner loops.
// grid (18, B*HEADS), block 128: thread = one query row
// ============================================================
__global__ __launch_bounds__(128) void attn_kernel(){
    int bh = blockIdx.y; int b = bh >> 3; int h = bh & 7;
    int tid = threadIdx.x;
    int n = blockIdx.x*128 + tid;
    __shared__ __align__(16) float Ks[32][36];
    __shared__ __align__(16) float Vs[32][36];
    __shared__ float bS[32];

    const float* Qr = d_Q + (bh*NPIX + n)*32;
    float q[32];
    #pragma unroll
    for (int i=0;i<8;i++){
        float4 t = *(const float4*)&Qr[i*4];
        q[i*4]=t.x; q[i*4+1]=t.y; q[i*4+2]=t.z; q[i*4+3]=t.w;
    }
    float m = -1e30f, l = 0.f;
    ull o2[16];
    #pragma unroll
    for (int i=0;i<16;i++) o2[i]=0ull;
    const float* KtB = d_Kt + bh*32*NPIX;
    const float* VB  = d_V  + bh*NPIX*32;
    const float* bb  = d_bias2 + b*NPIX;
    int rl = tid >> 2, cl = tid & 3;

    for (int t0=0; t0<NPIX; t0+=32){
        // Ks[d][j] = K^T[d][t0+j]  (column index j = token within tile)
        *(float4*)&Ks[rl][cl*4]      = *(const float4*)&KtB[rl*NPIX + t0 + cl*4];
        *(float4*)&Ks[rl][cl*4 + 16] = *(const float4*)&KtB[rl*NPIX + t0 + cl*4 + 16];
        // Vs[j][d] = V[t0+j][d]    (column index = dim; +16 applies to the DIM)
        *(float4*)&Vs[rl][cl*4]      = *(const float4*)&VB[(t0+rl)*32 + cl*4];
        *(float4*)&Vs[rl][cl*4 + 16] = *(const float4*)&VB[(t0+rl)*32 + cl*4 + 16];
        if (tid < 32) bS[tid] = bb[t0+tid];
        __syncthreads();

        // --- QK^T: s[j] for 32 keys, pairs via f32x2 ---
        ull s2[16];
        #pragma unroll
        for (int i=0;i<16;i++) s2[i]=0ull;
        #pragma unroll
        for (int d=0; d<32; d++){
            ull aa = pack1(q[d]);
            const ulonglong2* kr = (const ulonglong2*)&Ks[d][0];
            #pragma unroll
            for (int c=0;c<8;c++){
                ulonglong2 kk = kr[c];
                s2[2*c]   = fma2(aa, kk.x, s2[2*c]);
                s2[2*c+1] = fma2(aa, kk.y, s2[2*c+1]);
            }
        }
        // --- online softmax (base-2; scale folded into Q, bias includes log2e) ---
        float p[32];
        #pragma unroll
        for (int i=0;i<16;i++){
            float2 u = unpk(s2[i]);
            p[2*i]   = u.x + bS[2*i];
            p[2*i+1] = u.y + bS[2*i+1];
        }
        float mx = m;
        #pragma unroll
        for (int j=0;j<32;j++) mx = fmaxf(mx, p[j]);
        float corr = exp2f(m - mx); m = mx;
        float sum = 0.f;
        #pragma unroll
        for (int j=0;j<32;j++){ p[j] = exp2f(p[j]-m); sum += p[j]; }
        l = l*corr + sum;
        ull cc = pack1(corr);
        #pragma unroll
        for (int i=0;i<16;i++) o2[i]=mul2p(o2[i],cc);
        // --- PV ---
        #pragma unroll
        for (int j=0;j<32;j++){
            ull pp = pack1(p[j]);
            const ulonglong2* vr = (const ulonglong2*)&Vs[j][0];
            #pragma unroll
            for (int c=0;c<8;c++){
                ulonglong2 vv = vr[c];
                o2[2*c]   = fma2(pp, vv.x, o2[2*c]);
                o2[2*c+1] = fma2(pp, vv.y, o2[2*c+1]);
            }
        }
        __syncthreads();
    }
    float inv = 1.f/l;
    float* Orow = d_O + (b*Cn + h*32)*NPIX + n;
    #pragma unroll
    for (int i=0;i<16;i++){
        float2 u = unpk(o2[i]);
        Orow[(2*i)*NPIX]   = u.x*inv;
        Orow[(2*i+1)*NPIX] = u.y*inv;
    }
}

// ============================================================
// Kernel 8: output projection. Same GEMM scheme. grid (36,4,B)
// ============================================================
__global__ __launch_bounds__(256) void proj_kernel(const float* __restrict__ wproj,
        const float* __restrict__ bproj, float* __restrict__ out){
    int b = blockIdx.z;
    const float* X = d_O + b*Cn*NPIX;
    const float* W = wproj;
    __shared__ __align__(16) float As[16][68];
    __shared__ __align__(16) float Bs[16][64];
    int tid = threadIdx.x;
    int tx = tid & 15, ty = tid >> 4;
    int o0 = blockIdx.y*64, n0 = blockIdx.x*64;
    ull acc2[4][2];
    #pragma unroll
    for (int i=0;i<4;i++){ acc2[i][0]=0ull; acc2[i][1]=0ull; }
    int ra = tid >> 2, ca = tid & 3;
    int rb = tid >> 4, cb = tid & 15;
    for (int k0=0;k0<Cn;k0+=16){
        float4 a4 = *(const float4*)&W[(o0+ra)*Cn + k0 + ca*4];
        float4 b4 = *(const float4*)&X[(k0+rb)*NPIX + n0 + cb*4];
        As[ca*4+0][ra]=a4.x; As[ca*4+1][ra]=a4.y; As[ca*4+2][ra]=a4.z; As[ca*4+3][ra]=a4.w;
        *(float4*)&Bs[rb][cb*4] = b4;
        __syncthreads();
        #pragma unroll
        for (int k=0;k<16;k++){
            float4 bb4 = *(const float4*)&Bs[k][tx*4];
            ull bb0 = pack2(bb4.x, bb4.y), bb1 = pack2(bb4.z, bb4.w);
            float4 aa4 = *(const float4*)&As[k][ty*4];
            ull a0=pack1(aa4.x),a1=pack1(aa4.y),a2=pack1(aa4.z),a3=pack1(aa4.w);
            acc2[0][0]=fma2(a0,bb0,acc2[0][0]); acc2[0][1]=fma2(a0,bb1,acc2[0][1]);
            acc2[1][0]=fma2(a1,bb0,acc2[1][0]); acc2[1][1]=fma2(a1,bb1,acc2[1][1]);
            acc2[2][0]=fma2(a2,bb0,acc2[2][0]); acc2[2][1]=fma2(a2,bb1,acc2[2][1]);
            acc2[3][0]=fma2(a3,bb0,acc2[3][0]); acc2[3][1]=fma2(a3,bb1,acc2[3][1]);
        }
        __syncthreads();
    }
    #pragma unroll
    for (int i=0;i<4;i++){
        int o = o0 + ty*4 + i;
        float bo = bproj[o];
        float2 u0 = unpk(acc2[i][0]), u1 = unpk(acc2[i][1]);
        *(float4*)&out[(b*Cn+o)*NPIX + n0 + tx*4] =
            make_float4(u0.x+bo, u0.y+bo, u1.x+bo, u1.y+bo);
    }
}

// ============================================================
extern "C" void kernel_launch(void* const* d_in, const int* in_sizes, int n_in,
                              void* d_out, int out_size){
    const float* x      = (const float*)d_in[0];
    const float* rgb    = (const float*)d_in[1];
    const float* wq     = (const float*)d_in[2];
    const float* bq     = (const float*)d_in[3];
    const float* wk     = (const float*)d_in[4];
    const float* bk     = (const float*)d_in[5];
    const float* wv     = (const float*)d_in[6];
    const float* bv     = (const float*)d_in[7];
    const float* wproj  = (const float*)d_in[8];
    const float* bproj  = (const float*)d_in[9];
    const float* c1_w   = (const float*)d_in[10];
    const float* c1_b   = (const float*)d_in[11];
    const float* c2_w   = (const float*)d_in[12];
    const float* c2_b   = (const float*)d_in[13];
    const float* gq_w   = (const float*)d_in[14];
    const float* gq_b   = (const float*)d_in[15];
    const float* bqf_w  = (const float*)d_in[16];
    const float* bqf_b  = (const float*)d_in[17];
    const float* gk_w   = (const float*)d_in[18];
    const float* gk_b   = (const float*)d_in[19];
    const float* bkf_w  = (const float*)d_in[20];
    const float* bkf_b  = (const float*)d_in[21];
    const float* gv_w   = (const float*)d_in[22];
    const float* gv_b   = (const float*)d_in[23];
    const float* bvf_w  = (const float*)d_in[24];
    const float* bvf_b  = (const float*)d_in[25];
    const float* alpha  = (const float*)d_in[26];
    float* out = (float*)d_out;

    transpose_w2_kernel<<<(HIDn*HIDn*9 + 255)/256, 256>>>(c2_w);
    luma_kernel<<<Bn, 256>>>(rgb, alpha);
    conv1_kernel<<<dim3(HIDn, Bn), 256>>>(c1_w, c1_b);
    conv2_kernel<<<dim3(48, 2, Bn), 256>>>(c2_b);
    film_kernel<<<dim3(6, Bn), 256>>>(gq_w, gq_b, bqf_w, bqf_b,
                                      gk_w, gk_b, bkf_w, bkf_b,
                                      gv_w, gv_b, bvf_w, bvf_b);
    qkv_kernel<<<dim3(NPIX/64, Cn/64, Bn*3), 256>>>(x, wq, bq, wk, bk, wv, bv);
    attn_kernel<<<dim3(NPIX/128, Bn*8), 128>>>();
    proj_kernel<<<dim3(NPIX/64, Cn/64, Bn), 256>>>(wproj, bproj, out);
}